// round 14
// baseline (speedup 1.0000x reference)
#include <cuda_runtime.h>
#include <cuda_fp16.h>
#include <cstdint>

#define DEV_INLINE __device__ __forceinline__

// ------------------------- global scratch (no allocs allowed) -------------------------
__device__ __half g_adj16[100000000];         // adj * 2^14 as fp16 (200 MB)
__device__ __half g_feat16[10000 * 512];      // feature as fp16
__device__ __half g_W1T[256 * 512];           // W1^T fp16
__device__ __half g_W2T[64 * 256];            // W2^T fp16
__device__ __half g_S1T[256 * 10000];         // S1^T fp16
__device__ __half g_S2T[64 * 10000];          // S2^T fp16
__device__ __half g_x1h[10000 * 256];         // x1 as fp16 (for G3)
__device__ float  g_P1[8 * 10000 * 256];      // GEMM2 split-K partials [s][m][n] (scaled 2^14)
__device__ float  g_P2[8 * 10000 * 64];       // GEMM4 split-K partials [s][m][n] (scaled 2^14)

#define ADJ_SCALE 16384.0f
#define ADJ_INV   (1.0f / 16384.0f)

// ------------------------- helpers -------------------------
DEV_INLINE uint32_t smem_u32(const void* p) { return (uint32_t)__cvta_generic_to_shared(p); }

DEV_INLINE void cp_async16(uint32_t dst, const void* src, int bytes) {
    asm volatile("cp.async.cg.shared.global [%0], [%1], 16, %2;\n"
                 :: "r"(dst), "l"(src), "r"(bytes));
}
DEV_INLINE void cp_commit()  { asm volatile("cp.async.commit_group;\n" ::); }
DEV_INLINE void cp_wait_all(){ asm volatile("cp.async.wait_group 0;\n" ::); }

DEV_INLINE void mma_f16(float* c, const uint32_t* a, const uint32_t* b) {
    asm volatile(
        "mma.sync.aligned.m16n8k16.row.col.f32.f16.f16.f32 "
        "{%0,%1,%2,%3}, {%4,%5,%6,%7}, {%8,%9}, {%0,%1,%2,%3};\n"
        : "+f"(c[0]), "+f"(c[1]), "+f"(c[2]), "+f"(c[3])
        : "r"(a[0]), "r"(a[1]), "r"(a[2]), "r"(a[3]), "r"(b[0]), "r"(b[1]));
}

DEV_INLINE void ldsm4(uint32_t addr, uint32_t& r0, uint32_t& r1, uint32_t& r2, uint32_t& r3) {
    asm volatile("ldmatrix.sync.aligned.m8n8.x4.shared.b16 {%0,%1,%2,%3}, [%4];"
                 : "=r"(r0), "=r"(r1), "=r"(r2), "=r"(r3) : "r"(addr));
}

// ------------------------- gemm16: fp16 x fp16, 1 MMA pass -------------------------
// D[m,n] = sum_k A16[m,k] * BT[n,k].  A16 [M][lda], BT [N][ldb], K-major fp16.
// EPI 0: P[slice][m][Ntot] fp32 (grid.z = kSlices).  EPI 1: C[n][m] fp16 transposed (KS must be 1).
// PF 1: register-level fragment double-buffering (for the big G2 kernel).
template <int BM, int BN, int WARPS_M, int WARPS_N, int BKT, int EPI, int PF>
__global__ void __launch_bounds__(WARPS_M * WARPS_N * 32)
gemm16(const __half* __restrict__ A, int lda,
       const __half* __restrict__ B, int ldb,
       int M, int K, int Ntot, float* __restrict__ P, __half* __restrict__ C)
{
    constexpr int THREADS = WARPS_M * WARPS_N * 32;
    constexpr int WM = BM / WARPS_M;
    constexpr int WN = BN / WARPS_N;
    constexpr int MT = WM / 16;
    constexpr int NT = WN / 8;
    constexpr int ROWB = (BKT + 8) * 2;     // 144: row starts at banks 0,4,8,... ldsm conflict-free
    constexpr int AB = BM * ROWB;
    constexpr int BB = BN * ROWB;
    constexpr int OFF_B = AB;
    constexpr int STAGE = AB + BB;
    constexpr int SEG = BKT / 8;
    constexpr int NAC = BM * SEG / THREADS;
    constexpr int NBC = BN * SEG / THREADS;
    constexpr int KSTEPS = BKT / 16;

    extern __shared__ char sm[];
    const uint32_t smb = smem_u32(sm);

    const int tid  = threadIdx.x;
    const int warp = tid >> 5;
    const int lane = tid & 31;
    const int wm = warp / WARPS_N;
    const int wn = warp % WARPS_N;
    const int g  = lane >> 2;
    const int tg = lane & 3;

    const int aq_m = (lane & 7) + ((lane >> 3) & 1) * 8;
    const int aq_k = ((lane >> 4) & 1) * 8;
    const int bq_n = (lane & 7) + ((lane >> 4) & 1) * 8;
    const int bq_k = ((lane >> 3) & 1) * 8;

    const int m0 = blockIdx.x * BM;

    const int KS = gridDim.z, sl = blockIdx.z;
    const int nChTot = (K + BKT - 1) / BKT;
    const int cs = sl * nChTot / KS;
    const int ce = (sl + 1) * nChTot / KS;
    const int kB = cs * BKT;
    const int kE = min(ce * BKT, K);
    const int nCh = ce - cs;
    if (EPI == 0) P += (size_t)sl * M * Ntot;

    float acc[MT][NT][4];
    #pragma unroll
    for (int i = 0; i < MT; i++)
        #pragma unroll
        for (int j = 0; j < NT; j++)
            #pragma unroll
            for (int r = 0; r < 4; r++) acc[i][j][r] = 0.0f;

    auto ld = [&](int c, int s) {
        const int k0 = kB + c * BKT;
        #pragma unroll
        for (int i = 0; i < NAC; i++) {
            const int u = tid + i * THREADS;
            const int r = u / SEG, seg = u % SEG;
            const int kk = k0 + seg * 8;
            const int mg = m0 + r;
            const int by = (mg < M && kk + 8 <= kE) ? 16 : 0;
            const int mc = (mg < M) ? mg : (M - 1);
            cp_async16(smb + s * STAGE + r * ROWB + seg * 16,
                       A + (size_t)mc * lda + kk, by);
        }
        #pragma unroll
        for (int i = 0; i < NBC; i++) {
            const int u = tid + i * THREADS;
            const int r = u / SEG, seg = u % SEG;
            const int kk = k0 + seg * 8;
            const int by = (kk + 8 <= kE) ? 16 : 0;
            cp_async16(smb + s * STAGE + OFF_B + r * ROWB + seg * 16,
                       B + (size_t)r * ldb + kk, by);
        }
        cp_commit();
    };

    // prologue
    ld(0, 0);
    cp_wait_all();
    __syncthreads();

    for (int c = 0; c < nCh; c++) {
        const int s = c & 1;
        if (c + 1 < nCh) ld(c + 1, s ^ 1);

        const uint32_t base = smb + s * STAGE;
        const uint32_t aBase = base + (wm * WM + aq_m) * ROWB + aq_k * 2;
        const uint32_t bBase = base + OFF_B + (wn * WN + bq_n) * ROWB + bq_k * 2;

        if (PF) {
            // register double-buffered fragments: load kstep+1 while issuing kstep's MMAs
            uint32_t ah[2][MT][4], bh[2][NT / 2][4];
            #pragma unroll
            for (int mt = 0; mt < MT; mt++)
                ldsm4(aBase + mt * 16 * ROWB, ah[0][mt][0], ah[0][mt][1], ah[0][mt][2], ah[0][mt][3]);
            #pragma unroll
            for (int p = 0; p < NT / 2; p++)
                ldsm4(bBase + p * 16 * ROWB, bh[0][p][0], bh[0][p][1], bh[0][p][2], bh[0][p][3]);
            #pragma unroll
            for (int ks = 0; ks < KSTEPS; ks++) {
                const int cur = ks & 1;
                if (ks + 1 < KSTEPS) {
                    const int nxt = cur ^ 1;
                    const uint32_t ka = (ks + 1) * 32;   // 16 halfs = 32 bytes
                    #pragma unroll
                    for (int mt = 0; mt < MT; mt++)
                        ldsm4(aBase + mt * 16 * ROWB + ka, ah[nxt][mt][0], ah[nxt][mt][1], ah[nxt][mt][2], ah[nxt][mt][3]);
                    #pragma unroll
                    for (int p = 0; p < NT / 2; p++)
                        ldsm4(bBase + p * 16 * ROWB + ka, bh[nxt][p][0], bh[nxt][p][1], bh[nxt][p][2], bh[nxt][p][3]);
                }
                #pragma unroll
                for (int p = 0; p < NT / 2; p++)
                    #pragma unroll
                    for (int h = 0; h < 2; h++) {
                        const int nt = 2 * p + h;
                        #pragma unroll
                        for (int mt = 0; mt < MT; mt++)
                            mma_f16(acc[mt][nt], ah[cur][mt], bh[cur][p] + 2 * h);
                    }
            }
        } else {
            #pragma unroll
            for (int ks = 0; ks < KSTEPS; ks++) {
                const uint32_t ka = ks * 32;
                uint32_t ah[MT][4];
                #pragma unroll
                for (int mt = 0; mt < MT; mt++)
                    ldsm4(aBase + mt * 16 * ROWB + ka, ah[mt][0], ah[mt][1], ah[mt][2], ah[mt][3]);
                #pragma unroll
                for (int p = 0; p < NT / 2; p++) {
                    uint32_t bh[4];
                    ldsm4(bBase + p * 16 * ROWB + ka, bh[0], bh[1], bh[2], bh[3]);
                    #pragma unroll
                    for (int h = 0; h < 2; h++) {
                        const int nt = 2 * p + h;
                        #pragma unroll
                        for (int mt = 0; mt < MT; mt++)
                            mma_f16(acc[mt][nt], ah[mt], bh + 2 * h);
                    }
                }
            }
        }

        if (c + 1 < nCh) cp_wait_all();
        __syncthreads();
    }

    // ------------- epilogue -------------
    #pragma unroll
    for (int mt = 0; mt < MT; mt++) {
        const int r0 = m0 + wm * WM + mt * 16 + g;
        const int r1 = r0 + 8;
        #pragma unroll
        for (int nt = 0; nt < NT; nt++) {
            const int col = wn * WN + nt * 8 + 2 * tg;
            if (EPI == 0) {
                if (r0 < M) *(float2*)(P + (size_t)r0 * Ntot + col) = make_float2(acc[mt][nt][0], acc[mt][nt][1]);
                if (r1 < M) *(float2*)(P + (size_t)r1 * Ntot + col) = make_float2(acc[mt][nt][2], acc[mt][nt][3]);
            } else {
                if (r0 < M) {
                    C[(size_t)col * M + r0]       = __float2half(acc[mt][nt][0]);
                    C[(size_t)(col + 1) * M + r0] = __float2half(acc[mt][nt][1]);
                }
                if (r1 < M) {
                    C[(size_t)col * M + r1]       = __float2half(acc[mt][nt][2]);
                    C[(size_t)(col + 1) * M + r1] = __float2half(acc[mt][nt][3]);
                }
            }
        }
    }
}

// ------------------------- prep: adj -> fp16 (scaled 2^14) -------------------------
__global__ void prep_adj(const float* __restrict__ adj, int total8)
{
    const int i = blockIdx.x * blockDim.x + threadIdx.x;
    if (i >= total8) return;
    const float4* s = (const float4*)adj + 2 * (size_t)i;
    const float4 a = s[0], b = s[1];
    const __half2 h0 = __floats2half2_rn(a.x * ADJ_SCALE, a.y * ADJ_SCALE);
    const __half2 h1 = __floats2half2_rn(a.z * ADJ_SCALE, a.w * ADJ_SCALE);
    const __half2 h2 = __floats2half2_rn(b.x * ADJ_SCALE, b.y * ADJ_SCALE);
    const __half2 h3 = __floats2half2_rn(b.z * ADJ_SCALE, b.w * ADJ_SCALE);
    uint4 v;
    v.x = *(const uint32_t*)&h0; v.y = *(const uint32_t*)&h1;
    v.z = *(const uint32_t*)&h2; v.w = *(const uint32_t*)&h3;
    ((uint4*)g_adj16)[i] = v;
}

// ------------------------- prep: feature -> fp16; W1/W2 -> transposed fp16 -------------------------
__global__ void prep_feat(const float* __restrict__ feat, int total8)
{
    const int i = blockIdx.x * blockDim.x + threadIdx.x;
    if (i >= total8) return;
    const float4* s = (const float4*)feat + 2 * (size_t)i;
    const float4 a = s[0], b = s[1];
    const __half2 h0 = __floats2half2_rn(a.x, a.y);
    const __half2 h1 = __floats2half2_rn(a.z, a.w);
    const __half2 h2 = __floats2half2_rn(b.x, b.y);
    const __half2 h3 = __floats2half2_rn(b.z, b.w);
    uint4 v;
    v.x = *(const uint32_t*)&h0; v.y = *(const uint32_t*)&h1;
    v.z = *(const uint32_t*)&h2; v.w = *(const uint32_t*)&h3;
    ((uint4*)g_feat16)[i] = v;
}

__global__ void prep_weights(const float* __restrict__ W1, const float* __restrict__ W2)
{
    const int i = blockIdx.x * blockDim.x + threadIdx.x;
    if (i < 512 * 256) {
        const int k = i / 256, n = i % 256;
        g_W1T[n * 512 + k] = __float2half_rn(W1[i]);
    }
    if (i < 256 * 64) {
        const int k = i / 64, n = i % 64;
        g_W2T[n * 256 + k] = __float2half_rn(W2[i]);
    }
}

// ------------------------- reduce1: x1 = relu(inv*sum_s P1 + b1); also emits fp16 copy ------------
__global__ void reduce1(const float* __restrict__ b1, float* __restrict__ x1, int M, int KS)
{
    const int i = blockIdx.x * blockDim.x + threadIdx.x;   // float4 index
    const int tot = M * 64;
    if (i >= tot) return;
    const float4* P = (const float4*)g_P1;
    float4 v = P[i];
    for (int s = 1; s < KS; s++) {
        const float4 w = P[(size_t)s * tot + i];
        v.x += w.x; v.y += w.y; v.z += w.z; v.w += w.w;
    }
    const float4 b = ((const float4*)b1)[i & 63];
    v.x = fmaxf(v.x * ADJ_INV + b.x, 0.f); v.y = fmaxf(v.y * ADJ_INV + b.y, 0.f);
    v.z = fmaxf(v.z * ADJ_INV + b.z, 0.f); v.w = fmaxf(v.w * ADJ_INV + b.w, 0.f);
    ((float4*)x1)[i] = v;
    const __half2 h0 = __floats2half2_rn(v.x, v.y);
    const __half2 h1 = __floats2half2_rn(v.z, v.w);
    uint2 hv; hv.x = *(const uint32_t*)&h0; hv.y = *(const uint32_t*)&h1;
    ((uint2*)g_x1h)[i] = hv;
}

// ------------------------- reduce2: out2 = log_softmax(inv*sum_s P2 + b2) -------------------------
__global__ void reduce2(const float* __restrict__ b2, float* __restrict__ out2, int M, int KS)
{
    const int row = blockIdx.x * (blockDim.x >> 5) + (threadIdx.x >> 5);
    if (row >= M) return;
    const int lane = threadIdx.x & 31;
    const size_t tot = (size_t)M * 64;
    float v0 = 0.f, v1 = 0.f;
    for (int s = 0; s < KS; s++) {
        v0 += g_P2[s * tot + (size_t)row * 64 + lane];
        v1 += g_P2[s * tot + (size_t)row * 64 + lane + 32];
    }
    v0 = v0 * ADJ_INV + b2[lane];
    v1 = v1 * ADJ_INV + b2[lane + 32];
    float mx = fmaxf(v0, v1);
    #pragma unroll
    for (int o = 16; o > 0; o >>= 1) mx = fmaxf(mx, __shfl_xor_sync(0xffffffffu, mx, o));
    float ssum = __expf(v0 - mx) + __expf(v1 - mx);
    #pragma unroll
    for (int o = 16; o > 0; o >>= 1) ssum += __shfl_xor_sync(0xffffffffu, ssum, o);
    const float lse = mx + __logf(ssum);
    out2[(size_t)row * 64 + lane]      = v0 - lse;
    out2[(size_t)row * 64 + lane + 32] = v1 - lse;
}

// ------------------------- host -------------------------
extern "C" void kernel_launch(void* const* d_in, const int* in_sizes, int n_in,
                              void* d_out, int out_size)
{
    const float* feature = (const float*)d_in[0];
    const float* adj     = (const float*)d_in[1];
    const float* W1      = (const float*)d_in[2];
    const float* b1      = (const float*)d_in[3];
    const float* W2      = (const float*)d_in[4];
    const float* b2      = (const float*)d_in[5];

    const int hid  = in_sizes[3];              // 256
    const int fin  = in_sizes[2] / hid;        // 512
    const int n    = in_sizes[0] / fin;        // 10000

    // smem sizes: 2 stages of (BM+BN)*144
    constexpr int SM_G1 = 2 * (64 + 256) * 144;   //  92160
    constexpr int SM_G2 = 2 * (128 + 256) * 144;  // 110592
    constexpr int SM_G3 = 2 * (64 + 64) * 144;    //  36864
    constexpr int SM_G4 = 2 * (128 + 64) * 144;   //  55296
    cudaFuncSetAttribute((const void*)gemm16<64,256,1,8,64,1,0>,  cudaFuncAttributeMaxDynamicSharedMemorySize, SM_G1);
    cudaFuncSetAttribute((const void*)gemm16<128,256,2,4,64,0,1>, cudaFuncAttributeMaxDynamicSharedMemorySize, SM_G2);
    cudaFuncSetAttribute((const void*)gemm16<64,64,2,4,64,1,0>,   cudaFuncAttributeMaxDynamicSharedMemorySize, SM_G3);
    cudaFuncSetAttribute((const void*)gemm16<128,64,4,4,64,0,0>,  cudaFuncAttributeMaxDynamicSharedMemorySize, SM_G4);

    __half *adj16, *feat16, *w1t, *w2t, *s1t, *s2t, *x1h;
    float *p1, *p2;
    cudaGetSymbolAddress((void**)&adj16, g_adj16);
    cudaGetSymbolAddress((void**)&feat16, g_feat16);
    cudaGetSymbolAddress((void**)&w1t, g_W1T);    cudaGetSymbolAddress((void**)&w2t, g_W2T);
    cudaGetSymbolAddress((void**)&s1t, g_S1T);    cudaGetSymbolAddress((void**)&s2t, g_S2T);
    cudaGetSymbolAddress((void**)&x1h, g_x1h);
    cudaGetSymbolAddress((void**)&p1, g_P1);      cudaGetSymbolAddress((void**)&p2, g_P2);

    float* x1   = (float*)d_out;               // [n, 256]
    float* out2 = x1 + (size_t)n * hid;        // [n, 64]
    const int mb = (n + 127) / 128;            // 79
    const int mb64 = (n + 63) / 64;            // 157

    // 0) preps
    prep_weights<<<512, 256>>>(W1, W2);
    prep_feat<<<(n * fin / 8 + 255) / 256, 256>>>(feature, n * fin / 8);
    prep_adj<<<(n * n / 8 + 255) / 256, 256>>>(adj, n * n / 8);
    // 1) S1T = (feat16 @ W1T)^T  (1-pass fp16)
    gemm16<64,256,1,8,64,1,0><<<dim3(mb64, 1, 1), 256, SM_G1>>>(
        feat16, fin, w1t, fin, n, fin, hid, nullptr, s1t);
    // 2) P1[s] = adj16 @ S1 partials (split-K x7, frag prefetch)
    gemm16<128,256,2,4,64,0,1><<<dim3(mb, 1, 7), 256, SM_G2>>>(
        adj16, n, s1t, n, n, n, hid, p1, nullptr);
    // 3) x1 = relu(2^-14 * sum P1 + b1) -> d_out (+ fp16 copy for G3)
    reduce1<<<(n * 64 + 255) / 256, 256>>>(b1, x1, n, 7);
    // 4) S2T = (x1h @ W2T)^T  (1-pass fp16)
    gemm16<64,64,2,4,64,1,0><<<dim3(mb64, 1, 1), 256, SM_G3>>>(
        x1h, hid, w2t, hid, n, hid, 64, nullptr, s2t);
    // 5) P2[s] = adj16 @ S2 partials (split-K x8)
    gemm16<128,64,4,4,64,0,0><<<dim3(mb, 1, 8), 512, SM_G4>>>(
        adj16, n, s2t, n, n, n, 64, p2, nullptr);
    // 6) out2 = log_softmax(2^-14 * sum P2 + b2) -> d_out
    reduce2<<<(n + 3) / 4, 128>>>(b2, out2, n, 8);
}

// round 15
// speedup vs baseline: 1.2239x; 1.2239x over previous
#include <cuda_runtime.h>
#include <cuda_fp16.h>
#include <cstdint>

#define DEV_INLINE __device__ __forceinline__

// ------------------------- global scratch (no allocs allowed) -------------------------
__device__ __half g_adj16[100000000];         // adj * 2^14 as fp16 (written by G2, read by G4)
__device__ __half g_feat16[10000 * 512];      // feature as fp16
__device__ __half g_W1T[256 * 512];           // W1^T fp16
__device__ __half g_W2T[64 * 256];            // W2^T fp16
__device__ __half g_S1T[256 * 10000];         // S1^T fp16
__device__ __half g_S2T[64 * 10000];          // S2^T fp16
__device__ __half g_x1h[10000 * 256];         // x1 as fp16 (for G3)
__device__ float  g_P1[8 * 10000 * 256];      // GEMM2 split-K partials [s][m][n] (scaled 2^14)
__device__ float  g_P2[8 * 10000 * 64];       // GEMM4 split-K partials [s][m][n] (scaled 2^14)

#define ADJ_SCALE 16384.0f
#define ADJ_INV   (1.0f / 16384.0f)

// ------------------------- helpers -------------------------
DEV_INLINE uint32_t smem_u32(const void* p) { return (uint32_t)__cvta_generic_to_shared(p); }

DEV_INLINE void cp_async16(uint32_t dst, const void* src, int bytes) {
    asm volatile("cp.async.cg.shared.global [%0], [%1], 16, %2;\n"
                 :: "r"(dst), "l"(src), "r"(bytes));
}
DEV_INLINE void cp_commit()  { asm volatile("cp.async.commit_group;\n" ::); }
DEV_INLINE void cp_wait_all(){ asm volatile("cp.async.wait_group 0;\n" ::); }

DEV_INLINE void mma_f16(float* c, const uint32_t* a, const uint32_t* b) {
    asm volatile(
        "mma.sync.aligned.m16n8k16.row.col.f32.f16.f16.f32 "
        "{%0,%1,%2,%3}, {%4,%5,%6,%7}, {%8,%9}, {%0,%1,%2,%3};\n"
        : "+f"(c[0]), "+f"(c[1]), "+f"(c[2]), "+f"(c[3])
        : "r"(a[0]), "r"(a[1]), "r"(a[2]), "r"(a[3]), "r"(b[0]), "r"(b[1]));
}

DEV_INLINE void ldsm4(uint32_t addr, uint32_t& r0, uint32_t& r1, uint32_t& r2, uint32_t& r3) {
    asm volatile("ldmatrix.sync.aligned.m8n8.x4.shared.b16 {%0,%1,%2,%3}, [%4];"
                 : "=r"(r0), "=r"(r1), "=r"(r2), "=r"(r3) : "r"(addr));
}

DEV_INLINE uint32_t pack2h(float x0, float x1, float s) {
    const __half2 h = __floats2half2_rn(x0 * s, x1 * s);
    return *(const uint32_t*)&h;
}

// ------------------------- gemm16: fp16 x fp16, 1 MMA pass -------------------------
// D[m,n] = sum_k A16[m,k] * BT[n,k].  A16 [M][lda], BT [N][ldb], K-major fp16.
// EPI 0: P[slice][m][Ntot] fp32 (grid.z = kSlices).  EPI 1: C[n][m] fp16 transposed (KS=1).
template <int BM, int BN, int WARPS_M, int WARPS_N, int BKT, int EPI>
__global__ void __launch_bounds__(WARPS_M * WARPS_N * 32)
gemm16(const __half* __restrict__ A, int lda,
       const __half* __restrict__ B, int ldb,
       int M, int K, int Ntot, float* __restrict__ P, __half* __restrict__ C)
{
    constexpr int THREADS = WARPS_M * WARPS_N * 32;
    constexpr int WM = BM / WARPS_M;
    constexpr int WN = BN / WARPS_N;
    constexpr int MT = WM / 16;
    constexpr int NT = WN / 8;
    constexpr int ROWB = (BKT + 8) * 2;     // 144: row starts conflict-free for ldsm
    constexpr int AB = BM * ROWB;
    constexpr int BB = BN * ROWB;
    constexpr int OFF_B = AB;
    constexpr int STAGE = AB + BB;
    constexpr int SEG = BKT / 8;
    constexpr int NAC = BM * SEG / THREADS;
    constexpr int NBC = BN * SEG / THREADS;
    constexpr int KSTEPS = BKT / 16;

    extern __shared__ char sm[];
    const uint32_t smb = smem_u32(sm);

    const int tid  = threadIdx.x;
    const int warp = tid >> 5;
    const int lane = tid & 31;
    const int wm = warp / WARPS_N;
    const int wn = warp % WARPS_N;
    const int g  = lane >> 2;
    const int tg = lane & 3;

    const int aq_m = (lane & 7) + ((lane >> 3) & 1) * 8;
    const int aq_k = ((lane >> 4) & 1) * 8;
    const int bq_n = (lane & 7) + ((lane >> 4) & 1) * 8;
    const int bq_k = ((lane >> 3) & 1) * 8;

    const int m0 = blockIdx.x * BM;

    const int KS = gridDim.z, sl = blockIdx.z;
    const int nChTot = (K + BKT - 1) / BKT;
    const int cs = sl * nChTot / KS;
    const int ce = (sl + 1) * nChTot / KS;
    const int kB = cs * BKT;
    const int kE = min(ce * BKT, K);
    const int nCh = ce - cs;
    if (EPI == 0) P += (size_t)sl * M * Ntot;

    float acc[MT][NT][4];
    #pragma unroll
    for (int i = 0; i < MT; i++)
        #pragma unroll
        for (int j = 0; j < NT; j++)
            #pragma unroll
            for (int r = 0; r < 4; r++) acc[i][j][r] = 0.0f;

    auto ld = [&](int c, int s) {
        const int k0 = kB + c * BKT;
        #pragma unroll
        for (int i = 0; i < NAC; i++) {
            const int u = tid + i * THREADS;
            const int r = u / SEG, seg = u % SEG;
            const int kk = k0 + seg * 8;
            const int mg = m0 + r;
            const int by = (mg < M && kk + 8 <= kE) ? 16 : 0;
            const int mc = (mg < M) ? mg : (M - 1);
            cp_async16(smb + s * STAGE + r * ROWB + seg * 16,
                       A + (size_t)mc * lda + kk, by);
        }
        #pragma unroll
        for (int i = 0; i < NBC; i++) {
            const int u = tid + i * THREADS;
            const int r = u / SEG, seg = u % SEG;
            const int kk = k0 + seg * 8;
            const int by = (kk + 8 <= kE) ? 16 : 0;
            cp_async16(smb + s * STAGE + OFF_B + r * ROWB + seg * 16,
                       B + (size_t)r * ldb + kk, by);
        }
        cp_commit();
    };

    ld(0, 0);
    cp_wait_all();
    __syncthreads();

    for (int c = 0; c < nCh; c++) {
        const int s = c & 1;
        if (c + 1 < nCh) ld(c + 1, s ^ 1);

        const uint32_t base = smb + s * STAGE;
        const uint32_t aBase = base + (wm * WM + aq_m) * ROWB + aq_k * 2;
        const uint32_t bBase = base + OFF_B + (wn * WN + bq_n) * ROWB + bq_k * 2;

        #pragma unroll
        for (int ks = 0; ks < KSTEPS; ks++) {
            const uint32_t ka = ks * 32;
            uint32_t ah[MT][4];
            #pragma unroll
            for (int mt = 0; mt < MT; mt++)
                ldsm4(aBase + mt * 16 * ROWB + ka, ah[mt][0], ah[mt][1], ah[mt][2], ah[mt][3]);
            #pragma unroll
            for (int p = 0; p < NT / 2; p++) {
                uint32_t bh[4];
                ldsm4(bBase + p * 16 * ROWB + ka, bh[0], bh[1], bh[2], bh[3]);
                #pragma unroll
                for (int h = 0; h < 2; h++) {
                    const int nt = 2 * p + h;
                    #pragma unroll
                    for (int mt = 0; mt < MT; mt++)
                        mma_f16(acc[mt][nt], ah[mt], bh + 2 * h);
                }
            }
        }

        if (c + 1 < nCh) cp_wait_all();
        __syncthreads();
    }

    #pragma unroll
    for (int mt = 0; mt < MT; mt++) {
        const int r0 = m0 + wm * WM + mt * 16 + g;
        const int r1 = r0 + 8;
        #pragma unroll
        for (int nt = 0; nt < NT; nt++) {
            const int col = wn * WN + nt * 8 + 2 * tg;
            if (EPI == 0) {
                if (r0 < M) *(float2*)(P + (size_t)r0 * Ntot + col) = make_float2(acc[mt][nt][0], acc[mt][nt][1]);
                if (r1 < M) *(float2*)(P + (size_t)r1 * Ntot + col) = make_float2(acc[mt][nt][2], acc[mt][nt][3]);
            } else {
                if (r0 < M) {
                    C[(size_t)col * M + r0]       = __float2half(acc[mt][nt][0]);
                    C[(size_t)(col + 1) * M + r0] = __float2half(acc[mt][nt][1]);
                }
                if (r1 < M) {
                    C[(size_t)col * M + r1]       = __float2half(acc[mt][nt][2]);
                    C[(size_t)(col + 1) * M + r1] = __float2half(acc[mt][nt][3]);
                }
            }
        }
    }
}

// ------------------------- gemm16cv: A fp32 (convert in-loop, also emit fp16 copy) --------------
// For G2: A = adj fp32; converts A*2^14 -> fp16 into smem AND stores to Aout (g_adj16).
// B fp16 K-major.  Output fp32 partials P[slice][m][Ntot].  grid (mBlocks, 1, kSlices).
template <int BM, int BN, int WARPS_M, int WARPS_N, int BKT>
__global__ void __launch_bounds__(WARPS_M * WARPS_N * 32)
gemm16cv(const float* __restrict__ A, int lda, __half* __restrict__ Aout,
         const __half* __restrict__ B, int ldb,
         int M, int K, int Ntot, float* __restrict__ P)
{
    constexpr int THREADS = WARPS_M * WARPS_N * 32;   // 256
    constexpr int WM = BM / WARPS_M;                  // 64
    constexpr int WN = BN / WARPS_N;                  // 64
    constexpr int MT = WM / 16;                       // 4
    constexpr int NT = WN / 8;                        // 8
    constexpr int ROWB = (BKT + 8) * 2;               // 144
    constexpr int AB = BM * ROWB;
    constexpr int BB = BN * ROWB;
    constexpr int OFF_B = AB;
    constexpr int STAGE = AB + BB;
    constexpr int SEG = BKT / 8;
    constexpr int NBC = BN * SEG / THREADS;           // 8
    constexpr int NA4 = BM * BKT / 4 / THREADS;       // 8 float4 per thread
    constexpr int C4PR = BKT / 4;                     // float4 per row (16)
    constexpr int KSTEPS = BKT / 16;

    extern __shared__ char sm[];
    const uint32_t smb = smem_u32(sm);

    const int tid  = threadIdx.x;
    const int warp = tid >> 5;
    const int lane = tid & 31;
    const int wm = warp / WARPS_N;
    const int wn = warp % WARPS_N;
    const int g  = lane >> 2;
    const int tg = lane & 3;

    const int aq_m = (lane & 7) + ((lane >> 3) & 1) * 8;
    const int aq_k = ((lane >> 4) & 1) * 8;
    const int bq_n = (lane & 7) + ((lane >> 4) & 1) * 8;
    const int bq_k = ((lane >> 3) & 1) * 8;

    const int m0 = blockIdx.x * BM;

    const int KS = gridDim.z, sl = blockIdx.z;
    const int nChTot = (K + BKT - 1) / BKT;
    const int cs = sl * nChTot / KS;
    const int ce = (sl + 1) * nChTot / KS;
    const int kB = cs * BKT;
    const int kE = min(ce * BKT, K);
    const int nCh = ce - cs;
    P += (size_t)sl * M * Ntot;

    // thread's fixed A coords: row r, float4 col c4
    const int ar  = tid >> 5;                  // base row group: NA4 rows spaced
    const int ac4 = tid & (C4PR - 1);          // hmm need mapping over BM*C4PR items
    (void)ar; (void)ac4;

    float acc[MT][NT][4];
    #pragma unroll
    for (int i = 0; i < MT; i++)
        #pragma unroll
        for (int j = 0; j < NT; j++)
            #pragma unroll
            for (int r = 0; r < 4; r++) acc[i][j][r] = 0.0f;

    float4 aReg[NA4];

    auto ldA = [&](int c) {
        const int k0 = kB + c * BKT;
        #pragma unroll
        for (int i = 0; i < NA4; i++) {
            const int u = tid + i * THREADS;
            const int r = u / C4PR, c4 = u % C4PR;
            const int mg = m0 + r, kg = k0 + c4 * 4;
            aReg[i] = (mg < M && kg < kE) ? *(const float4*)(A + (size_t)mg * lda + kg)
                                          : make_float4(0.f, 0.f, 0.f, 0.f);
        }
    };
    auto stA = [&](int c, int s) {
        char* base = sm + s * STAGE;
        const int k0 = kB + c * BKT;
        #pragma unroll
        for (int i = 0; i < NA4; i++) {
            const int u = tid + i * THREADS;
            const int r = u / C4PR, c4 = u % C4PR;
            const int mg = m0 + r, kg = k0 + c4 * 4;
            uint2 hv;
            hv.x = pack2h(aReg[i].x, aReg[i].y, ADJ_SCALE);
            hv.y = pack2h(aReg[i].z, aReg[i].w, ADJ_SCALE);
            *(uint2*)(base + r * ROWB + c4 * 8) = hv;
            if (mg < M && kg < kE)
                *(uint2*)(Aout + (size_t)mg * lda + kg) = hv;
        }
    };
    auto ldB = [&](int c, int s) {
        const int k0 = kB + c * BKT;
        #pragma unroll
        for (int i = 0; i < NBC; i++) {
            const int u = tid + i * THREADS;
            const int r = u / SEG, seg = u % SEG;
            const int kk = k0 + seg * 8;
            const int by = (kk + 8 <= kE) ? 16 : 0;
            cp_async16(smb + s * STAGE + OFF_B + r * ROWB + seg * 16,
                       B + (size_t)r * ldb + kk, by);
        }
        cp_commit();
    };

    // prologue
    ldA(0);
    ldB(0, 0);
    cp_wait_all();
    stA(0, 0);
    __syncthreads();

    for (int c = 0; c < nCh; c++) {
        const int s = c & 1;
        if (c + 1 < nCh) { ldA(c + 1); ldB(c + 1, s ^ 1); }

        const uint32_t base = smb + s * STAGE;
        const uint32_t aBase = base + (wm * WM + aq_m) * ROWB + aq_k * 2;
        const uint32_t bBase = base + OFF_B + (wn * WN + bq_n) * ROWB + bq_k * 2;

        #pragma unroll
        for (int ks = 0; ks < KSTEPS; ks++) {
            const uint32_t ka = ks * 32;
            uint32_t ah[MT][4];
            #pragma unroll
            for (int mt = 0; mt < MT; mt++)
                ldsm4(aBase + mt * 16 * ROWB + ka, ah[mt][0], ah[mt][1], ah[mt][2], ah[mt][3]);
            #pragma unroll
            for (int p = 0; p < NT / 2; p++) {
                uint32_t bh[4];
                ldsm4(bBase + p * 16 * ROWB + ka, bh[0], bh[1], bh[2], bh[3]);
                #pragma unroll
                for (int h = 0; h < 2; h++) {
                    const int nt = 2 * p + h;
                    #pragma unroll
                    for (int mt = 0; mt < MT; mt++)
                        mma_f16(acc[mt][nt], ah[mt], bh + 2 * h);
                }
            }
        }

        if (c + 1 < nCh) { cp_wait_all(); stA(c + 1, s ^ 1); }
        __syncthreads();
    }

    #pragma unroll
    for (int mt = 0; mt < MT; mt++) {
        const int r0 = m0 + wm * WM + mt * 16 + g;
        const int r1 = r0 + 8;
        #pragma unroll
        for (int nt = 0; nt < NT; nt++) {
            const int col = wn * WN + nt * 8 + 2 * tg;
            if (r0 < M) *(float2*)(P + (size_t)r0 * Ntot + col) = make_float2(acc[mt][nt][0], acc[mt][nt][1]);
            if (r1 < M) *(float2*)(P + (size_t)r1 * Ntot + col) = make_float2(acc[mt][nt][2], acc[mt][nt][3]);
        }
    }
}

// ------------------------- prep: feature -> fp16; W1/W2 -> transposed fp16 -------------------------
__global__ void prep_feat(const float* __restrict__ feat, int total8)
{
    const int i = blockIdx.x * blockDim.x + threadIdx.x;
    if (i >= total8) return;
    const float4* s = (const float4*)feat + 2 * (size_t)i;
    const float4 a = s[0], b = s[1];
    uint4 v;
    v.x = pack2h(a.x, a.y, 1.0f); v.y = pack2h(a.z, a.w, 1.0f);
    v.z = pack2h(b.x, b.y, 1.0f); v.w = pack2h(b.z, b.w, 1.0f);
    ((uint4*)g_feat16)[i] = v;
}

__global__ void prep_weights(const float* __restrict__ W1, const float* __restrict__ W2)
{
    const int i = blockIdx.x * blockDim.x + threadIdx.x;
    if (i < 512 * 256) {
        const int k = i / 256, n = i % 256;
        g_W1T[n * 512 + k] = __float2half_rn(W1[i]);
    }
    if (i < 256 * 64) {
        const int k = i / 64, n = i % 64;
        g_W2T[n * 256 + k] = __float2half_rn(W2[i]);
    }
}

// ------------------------- reduce1: x1 = relu(inv*sum_s P1 + b1); dual fp32+fp16 ------------------
__global__ void reduce1(const float* __restrict__ b1, float* __restrict__ x1, int M, int KS)
{
    const int i = blockIdx.x * blockDim.x + threadIdx.x;   // float4 index
    const int tot = M * 64;
    if (i >= tot) return;
    const float4* P = (const float4*)g_P1;
    float4 v = P[i];
    for (int s = 1; s < KS; s++) {
        const float4 w = P[(size_t)s * tot + i];
        v.x += w.x; v.y += w.y; v.z += w.z; v.w += w.w;
    }
    const float4 b = ((const float4*)b1)[i & 63];
    v.x = fmaxf(v.x * ADJ_INV + b.x, 0.f); v.y = fmaxf(v.y * ADJ_INV + b.y, 0.f);
    v.z = fmaxf(v.z * ADJ_INV + b.z, 0.f); v.w = fmaxf(v.w * ADJ_INV + b.w, 0.f);
    ((float4*)x1)[i] = v;
    uint2 hv;
    hv.x = pack2h(v.x, v.y, 1.0f);
    hv.y = pack2h(v.z, v.w, 1.0f);
    ((uint2*)g_x1h)[i] = hv;
}

// ------------------------- reduce2: out2 = log_softmax(inv*sum_s P2 + b2) -------------------------
__global__ void reduce2(const float* __restrict__ b2, float* __restrict__ out2, int M, int KS)
{
    const int row = blockIdx.x * (blockDim.x >> 5) + (threadIdx.x >> 5);
    if (row >= M) return;
    const int lane = threadIdx.x & 31;
    const size_t tot = (size_t)M * 64;
    float v0 = 0.f, v1 = 0.f;
    for (int s = 0; s < KS; s++) {
        v0 += g_P2[s * tot + (size_t)row * 64 + lane];
        v1 += g_P2[s * tot + (size_t)row * 64 + lane + 32];
    }
    v0 = v0 * ADJ_INV + b2[lane];
    v1 = v1 * ADJ_INV + b2[lane + 32];
    float mx = fmaxf(v0, v1);
    #pragma unroll
    for (int o = 16; o > 0; o >>= 1) mx = fmaxf(mx, __shfl_xor_sync(0xffffffffu, mx, o));
    float ssum = __expf(v0 - mx) + __expf(v1 - mx);
    #pragma unroll
    for (int o = 16; o > 0; o >>= 1) ssum += __shfl_xor_sync(0xffffffffu, ssum, o);
    const float lse = mx + __logf(ssum);
    out2[(size_t)row * 64 + lane]      = v0 - lse;
    out2[(size_t)row * 64 + lane + 32] = v1 - lse;
}

// ------------------------- host -------------------------
extern "C" void kernel_launch(void* const* d_in, const int* in_sizes, int n_in,
                              void* d_out, int out_size)
{
    const float* feature = (const float*)d_in[0];
    const float* adj     = (const float*)d_in[1];
    const float* W1      = (const float*)d_in[2];
    const float* b1      = (const float*)d_in[3];
    const float* W2      = (const float*)d_in[4];
    const float* b2      = (const float*)d_in[5];

    const int hid  = in_sizes[3];              // 256
    const int fin  = in_sizes[2] / hid;        // 512
    const int n    = in_sizes[0] / fin;        // 10000

    constexpr int SM_G1 = 2 * (64 + 256) * 144;   //  92160
    constexpr int SM_G2 = 2 * (128 + 256) * 144;  // 110592
    constexpr int SM_G3 = 2 * (64 + 64) * 144;    //  36864
    constexpr int SM_G4 = 2 * (128 + 64) * 144;   //  55296
    cudaFuncSetAttribute((const void*)gemm16<64,256,1,8,64,1>,  cudaFuncAttributeMaxDynamicSharedMemorySize, SM_G1);
    cudaFuncSetAttribute((const void*)gemm16cv<128,256,2,4,64>, cudaFuncAttributeMaxDynamicSharedMemorySize, SM_G2);
    cudaFuncSetAttribute((const void*)gemm16<64,64,2,4,64,1>,   cudaFuncAttributeMaxDynamicSharedMemorySize, SM_G3);
    cudaFuncSetAttribute((const void*)gemm16<128,64,4,4,64,0>,  cudaFuncAttributeMaxDynamicSharedMemorySize, SM_G4);

    __half *adj16, *feat16, *w1t, *w2t, *s1t, *s2t, *x1h;
    float *p1, *p2;
    cudaGetSymbolAddress((void**)&adj16, g_adj16);
    cudaGetSymbolAddress((void**)&feat16, g_feat16);
    cudaGetSymbolAddress((void**)&w1t, g_W1T);    cudaGetSymbolAddress((void**)&w2t, g_W2T);
    cudaGetSymbolAddress((void**)&s1t, g_S1T);    cudaGetSymbolAddress((void**)&s2t, g_S2T);
    cudaGetSymbolAddress((void**)&x1h, g_x1h);
    cudaGetSymbolAddress((void**)&p1, g_P1);      cudaGetSymbolAddress((void**)&p2, g_P2);

    float* x1   = (float*)d_out;               // [n, 256]
    float* out2 = x1 + (size_t)n * hid;        // [n, 64]
    const int mb = (n + 127) / 128;            // 79
    const int mb64 = (n + 63) / 64;            // 157

    // 0) preps (no adj prep — fused into G2)
    prep_weights<<<512, 256>>>(W1, W2);
    prep_feat<<<(n * fin / 8 + 255) / 256, 256>>>(feature, n * fin / 8);
    // 1) S1T = (feat16 @ W1T)^T  (1-pass fp16)
    gemm16<64,256,1,8,64,1><<<dim3(mb64, 1, 1), 256, SM_G1>>>(
        feat16, fin, w1t, fin, n, fin, hid, nullptr, s1t);
    // 2) P1[s] = (adj*2^14) @ S1 partials; converts adj fp32->fp16 in-loop AND writes g_adj16
    gemm16cv<128,256,2,4,64><<<dim3(mb, 1, 7), 256, SM_G2>>>(
        adj, n, adj16, s1t, n, n, n, hid, p1);
    // 3) x1 = relu(2^-14 * sum P1 + b1) -> d_out (+ fp16 copy for G3)
    reduce1<<<(n * 64 + 255) / 256, 256>>>(b1, x1, n, 7);
    // 4) S2T = (x1h @ W2T)^T  (1-pass fp16)
    gemm16<64,64,2,4,64,1><<<dim3(mb64, 1, 1), 256, SM_G3>>>(
        x1h, hid, w2t, hid, n, hid, 64, nullptr, s2t);
    // 5) P2[s] = adj16 @ S2 partials (adj16 written by G2; same-stream ordering)
    gemm16<128,64,4,4,64,0><<<dim3(mb, 1, 8), 512, SM_G4>>>(
        adj16, n, s2t, n, n, n, 64, p2, nullptr);
    // 6) out2 = log_softmax(2^-14 * sum P2 + b2) -> d_out
    reduce2<<<(n + 3) / 4, 128>>>(b2, out2, n, 8);
}

// round 17
// speedup vs baseline: 1.2571x; 1.0271x over previous
#include <cuda_runtime.h>
#include <cuda_fp16.h>
#include <cstdint>

#define DEV_INLINE __device__ __forceinline__

// ------------------------- global scratch (no allocs allowed) -------------------------
__device__ __half g_adj16[100000000];         // adj * 2^14 as fp16 (written by G2, read by G4)
__device__ __half g_feat16[10000 * 512];      // feature as fp16
__device__ __half g_W1T[256 * 512];           // W1^T fp16
__device__ __half g_W2T[64 * 256];            // W2^T fp16
__device__ __half g_S1T[256 * 10000];         // S1^T fp16
__device__ __half g_S2T[64 * 10000];          // S2^T fp16
__device__ __half g_x1h[10000 * 256];         // x1 as fp16 (for G3)
__device__ float  g_P1[8 * 10000 * 256];      // GEMM2 split-K partials [s][m][n] (scaled 2^14)
__device__ float  g_P2[8 * 10000 * 64];       // GEMM4 split-K partials [s][m][n] (scaled 2^14)

#define ADJ_SCALE 16384.0f
#define ADJ_INV   (1.0f / 16384.0f)

// ------------------------- helpers -------------------------
DEV_INLINE uint32_t smem_u32(const void* p) { return (uint32_t)__cvta_generic_to_shared(p); }

DEV_INLINE void cp_async16(uint32_t dst, const void* src, int bytes) {
    asm volatile("cp.async.cg.shared.global [%0], [%1], 16, %2;\n"
                 :: "r"(dst), "l"(src), "r"(bytes));
}
DEV_INLINE void cp_commit()  { asm volatile("cp.async.commit_group;\n" ::); }
DEV_INLINE void cp_wait_all(){ asm volatile("cp.async.wait_group 0;\n" ::); }

DEV_INLINE void mma_f16(float* c, const uint32_t* a, const uint32_t* b) {
    asm volatile(
        "mma.sync.aligned.m16n8k16.row.col.f32.f16.f16.f32 "
        "{%0,%1,%2,%3}, {%4,%5,%6,%7}, {%8,%9}, {%0,%1,%2,%3};\n"
        : "+f"(c[0]), "+f"(c[1]), "+f"(c[2]), "+f"(c[3])
        : "r"(a[0]), "r"(a[1]), "r"(a[2]), "r"(a[3]), "r"(b[0]), "r"(b[1]));
}

DEV_INLINE void ldsm4(uint32_t addr, uint32_t& r0, uint32_t& r1, uint32_t& r2, uint32_t& r3) {
    asm volatile("ldmatrix.sync.aligned.m8n8.x4.shared.b16 {%0,%1,%2,%3}, [%4];"
                 : "=r"(r0), "=r"(r1), "=r"(r2), "=r"(r3) : "r"(addr));
}

DEV_INLINE uint32_t pack2h(float x0, float x1, float s) {
    const __half2 h = __floats2half2_rn(x0 * s, x1 * s);
    return *(const uint32_t*)&h;
}

// ------------------------- gemm16: fp16 x fp16, 1 MMA pass -------------------------
// D[m,n] = sum_k A16[m,k] * BT[n,k].  A16 [M][lda], BT [N][ldb], K-major fp16.
// EPI 0: P[slice][m][Ntot] fp32 (grid.z = kSlices).  EPI 1: C[n][m] fp16 transposed (KS=1).
template <int BM, int BN, int WARPS_M, int WARPS_N, int BKT, int EPI>
__global__ void __launch_bounds__(WARPS_M * WARPS_N * 32)
gemm16(const __half* __restrict__ A, int lda,
       const __half* __restrict__ B, int ldb,
       int M, int K, int Ntot, float* __restrict__ P, __half* __restrict__ C)
{
    constexpr int THREADS = WARPS_M * WARPS_N * 32;
    constexpr int WM = BM / WARPS_M;
    constexpr int WN = BN / WARPS_N;
    constexpr int MT = WM / 16;
    constexpr int NT = WN / 8;
    constexpr int ROWB = (BKT + 8) * 2;     // 144/272: row starts conflict-free for ldsm
    constexpr int AB = BM * ROWB;
    constexpr int BB = BN * ROWB;
    constexpr int OFF_B = AB;
    constexpr int STAGE = AB + BB;
    constexpr int SEG = BKT / 8;
    constexpr int NAC = BM * SEG / THREADS;
    constexpr int NBC = BN * SEG / THREADS;
    constexpr int KSTEPS = BKT / 16;

    extern __shared__ char sm[];
    const uint32_t smb = smem_u32(sm);

    const int tid  = threadIdx.x;
    const int warp = tid >> 5;
    const int lane = tid & 31;
    const int wm = warp / WARPS_N;
    const int wn = warp % WARPS_N;
    const int g  = lane >> 2;
    const int tg = lane & 3;

    const int aq_m = (lane & 7) + ((lane >> 3) & 1) * 8;
    const int aq_k = ((lane >> 4) & 1) * 8;
    const int bq_n = (lane & 7) + ((lane >> 4) & 1) * 8;
    const int bq_k = ((lane >> 3) & 1) * 8;

    const int m0 = blockIdx.x * BM;

    const int KS = gridDim.z, sl = blockIdx.z;
    const int nChTot = (K + BKT - 1) / BKT;
    const int cs = sl * nChTot / KS;
    const int ce = (sl + 1) * nChTot / KS;
    const int kB = cs * BKT;
    const int kE = min(ce * BKT, K);
    const int nCh = ce - cs;
    if (EPI == 0) P += (size_t)sl * M * Ntot;

    float acc[MT][NT][4];
    #pragma unroll
    for (int i = 0; i < MT; i++)
        #pragma unroll
        for (int j = 0; j < NT; j++)
            #pragma unroll
            for (int r = 0; r < 4; r++) acc[i][j][r] = 0.0f;

    auto ld = [&](int c, int s) {
        const int k0 = kB + c * BKT;
        #pragma unroll
        for (int i = 0; i < NAC; i++) {
            const int u = tid + i * THREADS;
            const int r = u / SEG, seg = u % SEG;
            const int kk = k0 + seg * 8;
            const int mg = m0 + r;
            const int by = (mg < M && kk + 8 <= kE) ? 16 : 0;
            const int mc = (mg < M) ? mg : (M - 1);
            cp_async16(smb + s * STAGE + r * ROWB + seg * 16,
                       A + (size_t)mc * lda + kk, by);
        }
        #pragma unroll
        for (int i = 0; i < NBC; i++) {
            const int u = tid + i * THREADS;
            const int r = u / SEG, seg = u % SEG;
            const int kk = k0 + seg * 8;
            const int by = (kk + 8 <= kE) ? 16 : 0;
            cp_async16(smb + s * STAGE + OFF_B + r * ROWB + seg * 16,
                       B + (size_t)r * ldb + kk, by);
        }
        cp_commit();
    };

    ld(0, 0);
    cp_wait_all();
    __syncthreads();

    for (int c = 0; c < nCh; c++) {
        const int s = c & 1;
        if (c + 1 < nCh) ld(c + 1, s ^ 1);

        const uint32_t base = smb + s * STAGE;
        const uint32_t aBase = base + (wm * WM + aq_m) * ROWB + aq_k * 2;
        const uint32_t bBase = base + OFF_B + (wn * WN + bq_n) * ROWB + bq_k * 2;

        #pragma unroll
        for (int ks = 0; ks < KSTEPS; ks++) {
            const uint32_t ka = ks * 32;
            uint32_t ah[MT][4];
            #pragma unroll
            for (int mt = 0; mt < MT; mt++)
                ldsm4(aBase + mt * 16 * ROWB + ka, ah[mt][0], ah[mt][1], ah[mt][2], ah[mt][3]);
            #pragma unroll
            for (int p = 0; p < NT / 2; p++) {
                uint32_t bh[4];
                ldsm4(bBase + p * 16 * ROWB + ka, bh[0], bh[1], bh[2], bh[3]);
                #pragma unroll
                for (int h = 0; h < 2; h++) {
                    const int nt = 2 * p + h;
                    #pragma unroll
                    for (int mt = 0; mt < MT; mt++)
                        mma_f16(acc[mt][nt], ah[mt], bh + 2 * h);
                }
            }
        }

        if (c + 1 < nCh) cp_wait_all();
        __syncthreads();
    }

    #pragma unroll
    for (int mt = 0; mt < MT; mt++) {
        const int r0 = m0 + wm * WM + mt * 16 + g;
        const int r1 = r0 + 8;
        #pragma unroll
        for (int nt = 0; nt < NT; nt++) {
            const int col = wn * WN + nt * 8 + 2 * tg;
            if (EPI == 0) {
                if (r0 < M) *(float2*)(P + (size_t)r0 * Ntot + col) = make_float2(acc[mt][nt][0], acc[mt][nt][1]);
                if (r1 < M) *(float2*)(P + (size_t)r1 * Ntot + col) = make_float2(acc[mt][nt][2], acc[mt][nt][3]);
            } else {
                if (r0 < M) {
                    C[(size_t)col * M + r0]       = __float2half(acc[mt][nt][0]);
                    C[(size_t)(col + 1) * M + r0] = __float2half(acc[mt][nt][1]);
                }
                if (r1 < M) {
                    C[(size_t)col * M + r1]       = __float2half(acc[mt][nt][2]);
                    C[(size_t)(col + 1) * M + r1] = __float2half(acc[mt][nt][3]);
                }
            }
        }
    }
}

// ------------------------- gemm16cv: A fp32 (convert in-loop, also emit fp16 copy) --------------
// For G2: A = adj fp32; converts A*2^14 -> fp16 into smem AND stores to Aout (g_adj16).
// B fp16 K-major.  Output fp32 partials P[slice][m][Ntot].  grid (mBlocks, 1, kSlices).
template <int BM, int BN, int WARPS_M, int WARPS_N, int BKT>
__global__ void __launch_bounds__(WARPS_M * WARPS_N * 32)
gemm16cv(const float* __restrict__ A, int lda, __half* __restrict__ Aout,
         const __half* __restrict__ B, int ldb,
         int M, int K, int Ntot, float* __restrict__ P)
{
    constexpr int THREADS = WARPS_M * WARPS_N * 32;   // 512
    constexpr int WM = BM / WARPS_M;                  // 64
    constexpr int WN = BN / WARPS_N;                  // 32
    constexpr int MT = WM / 16;                       // 4
    constexpr int NT = WN / 8;                        // 4
    constexpr int ROWB = (BKT + 8) * 2;               // 144
    constexpr int AB = BM * ROWB;
    constexpr int BB = BN * ROWB;
    constexpr int OFF_B = AB;
    constexpr int STAGE = AB + BB;
    constexpr int SEG = BKT / 8;
    constexpr int NBC = BN * SEG / THREADS;           // 4
    constexpr int NA4 = BM * BKT / 4 / THREADS;       // 4 float4 per thread
    constexpr int C4PR = BKT / 4;                     // float4 per row (16)
    constexpr int KSTEPS = BKT / 16;

    extern __shared__ char sm[];
    const uint32_t smb = smem_u32(sm);

    const int tid  = threadIdx.x;
    const int warp = tid >> 5;
    const int lane = tid & 31;
    const int wm = warp / WARPS_N;
    const int wn = warp % WARPS_N;
    const int g  = lane >> 2;
    const int tg = lane & 3;

    const int aq_m = (lane & 7) + ((lane >> 3) & 1) * 8;
    const int aq_k = ((lane >> 4) & 1) * 8;
    const int bq_n = (lane & 7) + ((lane >> 4) & 1) * 8;
    const int bq_k = ((lane >> 3) & 1) * 8;

    const int m0 = blockIdx.x * BM;

    const int KS = gridDim.z, sl = blockIdx.z;
    const int nChTot = (K + BKT - 1) / BKT;
    const int cs = sl * nChTot / KS;
    const int ce = (sl + 1) * nChTot / KS;
    const int kB = cs * BKT;
    const int kE = min(ce * BKT, K);
    const int nCh = ce - cs;
    P += (size_t)sl * M * Ntot;

    float acc[MT][NT][4];
    #pragma unroll
    for (int i = 0; i < MT; i++)
        #pragma unroll
        for (int j = 0; j < NT; j++)
            #pragma unroll
            for (int r = 0; r < 4; r++) acc[i][j][r] = 0.0f;

    float4 aReg[NA4];

    auto ldA = [&](int c) {
        const int k0 = kB + c * BKT;
        #pragma unroll
        for (int i = 0; i < NA4; i++) {
            const int u = tid + i * THREADS;
            const int r = u / C4PR, c4 = u % C4PR;
            const int mg = m0 + r, kg = k0 + c4 * 4;
            aReg[i] = (mg < M && kg < kE) ? *(const float4*)(A + (size_t)mg * lda + kg)
                                          : make_float4(0.f, 0.f, 0.f, 0.f);
        }
    };
    auto stA = [&](int c, int s) {
        char* base = sm + s * STAGE;
        const int k0 = kB + c * BKT;
        #pragma unroll
        for (int i = 0; i < NA4; i++) {
            const int u = tid + i * THREADS;
            const int r = u / C4PR, c4 = u % C4PR;
            const int mg = m0 + r, kg = k0 + c4 * 4;
            uint2 hv;
            hv.x = pack2h(aReg[i].x, aReg[i].y, ADJ_SCALE);
            hv.y = pack2h(aReg[i].z, aReg[i].w, ADJ_SCALE);
            *(uint2*)(base + r * ROWB + c4 * 8) = hv;
            if (mg < M && kg < kE)
                *(uint2*)(Aout + (size_t)mg * lda + kg) = hv;
        }
    };
    auto ldB = [&](int c, int s) {
        const int k0 = kB + c * BKT;
        #pragma unroll
        for (int i = 0; i < NBC; i++) {
            const int u = tid + i * THREADS;
            const int r = u / SEG, seg = u % SEG;
            const int kk = k0 + seg * 8;
            const int by = (kk + 8 <= kE) ? 16 : 0;
            cp_async16(smb + s * STAGE + OFF_B + r * ROWB + seg * 16,
                       B + (size_t)r * ldb + kk, by);
        }
        cp_commit();
    };

    // prologue
    ldA(0);
    ldB(0, 0);
    cp_wait_all();
    stA(0, 0);
    __syncthreads();

    for (int c = 0; c < nCh; c++) {
        const int s = c & 1;
        if (c + 1 < nCh) { ldA(c + 1); ldB(c + 1, s ^ 1); }

        const uint32_t base = smb + s * STAGE;
        const uint32_t aBase = base + (wm * WM + aq_m) * ROWB + aq_k * 2;
        const uint32_t bBase = base + OFF_B + (wn * WN + bq_n) * ROWB + bq_k * 2;

        #pragma unroll
        for (int ks = 0; ks < KSTEPS; ks++) {
            const uint32_t ka = ks * 32;
            uint32_t ah[MT][4];
            #pragma unroll
            for (int mt = 0; mt < MT; mt++)
                ldsm4(aBase + mt * 16 * ROWB + ka, ah[mt][0], ah[mt][1], ah[mt][2], ah[mt][3]);
            #pragma unroll
            for (int p = 0; p < NT / 2; p++) {
                uint32_t bh[4];
                ldsm4(bBase + p * 16 * ROWB + ka, bh[0], bh[1], bh[2], bh[3]);
                #pragma unroll
                for (int h = 0; h < 2; h++) {
                    const int nt = 2 * p + h;
                    #pragma unroll
                    for (int mt = 0; mt < MT; mt++)
                        mma_f16(acc[mt][nt], ah[mt], bh + 2 * h);
                }
            }
        }

        if (c + 1 < nCh) { cp_wait_all(); stA(c + 1, s ^ 1); }
        __syncthreads();
    }

    #pragma unroll
    for (int mt = 0; mt < MT; mt++) {
        const int r0 = m0 + wm * WM + mt * 16 + g;
        const int r1 = r0 + 8;
        #pragma unroll
        for (int nt = 0; nt < NT; nt++) {
            const int col = wn * WN + nt * 8 + 2 * tg;
            if (r0 < M) *(float2*)(P + (size_t)r0 * Ntot + col) = make_float2(acc[mt][nt][0], acc[mt][nt][1]);
            if (r1 < M) *(float2*)(P + (size_t)r1 * Ntot + col) = make_float2(acc[mt][nt][2], acc[mt][nt][3]);
        }
    }
}

// ------------------------- preps -------------------------
__global__ void prep_feat(const float* __restrict__ feat, int total8)
{
    const int i = blockIdx.x * blockDim.x + threadIdx.x;
    if (i >= total8) return;
    const float4* s = (const float4*)feat + 2 * (size_t)i;
    const float4 a = s[0], b = s[1];
    uint4 v;
    v.x = pack2h(a.x, a.y, 1.0f); v.y = pack2h(a.z, a.w, 1.0f);
    v.z = pack2h(b.x, b.y, 1.0f); v.w = pack2h(b.z, b.w, 1.0f);
    ((uint4*)g_feat16)[i] = v;
}

__global__ void prep_weights(const float* __restrict__ W1, const float* __restrict__ W2)
{
    const int i = blockIdx.x * blockDim.x + threadIdx.x;
    if (i < 512 * 256) {
        const int k = i / 256, n = i % 256;
        g_W1T[n * 512 + k] = __float2half_rn(W1[i]);
    }
    if (i < 256 * 64) {
        const int k = i / 64, n = i % 64;
        g_W2T[n * 256 + k] = __float2half_rn(W2[i]);
    }
}

// ------------------------- reduce1: x1 = relu(inv*sum_s P1 + b1); dual fp32+fp16 ------------------
__global__ void reduce1(const float* __restrict__ b1, float* __restrict__ x1, int M, int KS)
{
    const int i = blockIdx.x * blockDim.x + threadIdx.x;   // float4 index
    const int tot = M * 64;
    if (i >= tot) return;
    const float4* P = (const float4*)g_P1;
    float4 v = P[i];
    for (int s = 1; s < KS; s++) {
        const float4 w = P[(size_t)s * tot + i];
        v.x += w.x; v.y += w.y; v.z += w.z; v.w += w.w;
    }
    const float4 b = ((const float4*)b1)[i & 63];
    v.x = fmaxf(v.x * ADJ_INV + b.x, 0.f); v.y = fmaxf(v.y * ADJ_INV + b.y, 0.f);
    v.z = fmaxf(v.z * ADJ_INV + b.z, 0.f); v.w = fmaxf(v.w * ADJ_INV + b.w, 0.f);
    ((float4*)x1)[i] = v;
    uint2 hv;
    hv.x = pack2h(v.x, v.y, 1.0f);
    hv.y = pack2h(v.z, v.w, 1.0f);
    ((uint2*)g_x1h)[i] = hv;
}

// ------------------------- reduce2: out2 = log_softmax(inv*sum_s P2 + b2) -------------------------
__global__ void reduce2(const float* __restrict__ b2, float* __restrict__ out2, int M, int KS)
{
    const int row = blockIdx.x * (blockDim.x >> 5) + (threadIdx.x >> 5);
    if (row >= M) return;
    const int lane = threadIdx.x & 31;
    const size_t tot = (size_t)M * 64;
    float v0 = 0.f, v1 = 0.f;
    for (int s = 0; s < KS; s++) {
        v0 += g_P2[s * tot + (size_t)row * 64 + lane];
        v1 += g_P2[s * tot + (size_t)row * 64 + lane + 32];
    }
    v0 = v0 * ADJ_INV + b2[lane];
    v1 = v1 * ADJ_INV + b2[lane + 32];
    float mx = fmaxf(v0, v1);
    #pragma unroll
    for (int o = 16; o > 0; o >>= 1) mx = fmaxf(mx, __shfl_xor_sync(0xffffffffu, mx, o));
    float ssum = __expf(v0 - mx) + __expf(v1 - mx);
    #pragma unroll
    for (int o = 16; o > 0; o >>= 1) ssum += __shfl_xor_sync(0xffffffffu, ssum, o);
    const float lse = mx + __logf(ssum);
    out2[(size_t)row * 64 + lane]      = v0 - lse;
    out2[(size_t)row * 64 + lane + 32] = v1 - lse;
}

// ------------------------- host -------------------------
extern "C" void kernel_launch(void* const* d_in, const int* in_sizes, int n_in,
                              void* d_out, int out_size)
{
    const float* feature = (const float*)d_in[0];
    const float* adj     = (const float*)d_in[1];
    const float* W1      = (const float*)d_in[2];
    const float* b1      = (const float*)d_in[3];
    const float* W2      = (const float*)d_in[4];
    const float* b2      = (const float*)d_in[5];

    const int hid  = in_sizes[3];              // 256
    const int fin  = in_sizes[2] / hid;        // 512
    const int n    = in_sizes[0] / fin;        // 10000

    constexpr int SM_G1 = 2 * (64 + 256) * 272;   // 174080 (BKT=128)
    constexpr int SM_G2 = 2 * (128 + 256) * 144;  // 110592 (BKT=64)
    constexpr int SM_G3 = 2 * (64 + 64) * 272;    //  69632 (BKT=128)
    constexpr int SM_G4 = 2 * (128 + 64) * 272;   // 104448 (BKT=128)
    cudaFuncSetAttribute((const void*)gemm16<64,256,1,8,128,1>, cudaFuncAttributeMaxDynamicSharedMemorySize, SM_G1);
    cudaFuncSetAttribute((const void*)gemm16cv<128,256,2,8,64>, cudaFuncAttributeMaxDynamicSharedMemorySize, SM_G2);
    cudaFuncSetAttribute((const void*)gemm16<64,64,2,4,128,1>,  cudaFuncAttributeMaxDynamicSharedMemorySize, SM_G3);
    cudaFuncSetAttribute((const void*)gemm16<128,64,4,4,128,0>, cudaFuncAttributeMaxDynamicSharedMemorySize, SM_G4);

    __half *adj16, *feat16, *w1t, *w2t, *s1t, *s2t, *x1h;
    float *p1, *p2;
    cudaGetSymbolAddress((void**)&adj16, g_adj16);
    cudaGetSymbolAddress((void**)&feat16, g_feat16);
    cudaGetSymbolAddress((void**)&w1t, g_W1T);    cudaGetSymbolAddress((void**)&w2t, g_W2T);
    cudaGetSymbolAddress((void**)&s1t, g_S1T);    cudaGetSymbolAddress((void**)&s2t, g_S2T);
    cudaGetSymbolAddress((void**)&x1h, g_x1h);
    cudaGetSymbolAddress((void**)&p1, g_P1);      cudaGetSymbolAddress((void**)&p2, g_P2);

    float* x1   = (float*)d_out;               // [n, 256]
    float* out2 = x1 + (size_t)n * hid;        // [n, 64]
    const int mb = (n + 127) / 128;            // 79
    const int mb64 = (n + 63) / 64;            // 157

    // 0) preps (adj conversion fused into G2)
    prep_weights<<<512, 256>>>(W1, W2);
    prep_feat<<<(n * fin / 8 + 255) / 256, 256>>>(feature, n * fin / 8);
    // 1) S1T = (feat16 @ W1T)^T  (1-pass fp16, BKT=128)
    gemm16<64,256,1,8,128,1><<<dim3(mb64, 1, 1), 256, SM_G1>>>(
        feat16, fin, w1t, fin, n, fin, hid, nullptr, s1t);
    // 2) P1[s] = (adj*2^14) @ S1 partials; converts adj fp32->fp16 AND writes g_adj16 (16 warps)
    gemm16cv<128,256,2,8,64><<<dim3(mb, 1, 7), 512, SM_G2>>>(
        adj, n, adj16, s1t, n, n, n, hid, p1);
    // 3) x1 = relu(2^-14 * sum P1 + b1) -> d_out (+ fp16 copy for G3)
    reduce1<<<(n * 64 + 255) / 256, 256>>>(b1, x1, n, 7);
    // 4) S2T = (x1h @ W2T)^T  (1-pass fp16, BKT=128)
    gemm16<64,64,2,4,128,1><<<dim3(mb64, 1, 1), 256, SM_G3>>>(
        x1h, hid, w2t, hid, n, hid, 64, nullptr, s2t);
    // 5) P2[s] = adj16 @ S2 partials (BKT=128, split-K x8)
    gemm16<128,64,4,4,128,0><<<dim3(mb, 1, 8), 512, SM_G4>>>(
        adj16, n, s2t, n, n, n, 64, p2, nullptr);
    // 6) out2 = log_softmax(2^-14 * sum P2 + b2) -> d_out
    reduce2<<<(n + 3) / 4, 128>>>(b2, out2, n, 8);
}